// round 13
// baseline (speedup 1.0000x reference)
#include <cuda_runtime.h>
#include <cuda_fp16.h>
#include <math.h>
#include <stdint.h>

// GraphSAGE encoder:
//   CSR build (3 launches, 4 edges/thread) -> fp16 gather/mean (8 lanes/group,
//   2 nodes/group dual-stream, LDG.128, MLP-16, zero-row padding, no tail)
//   -> HMMA transform (layer 2 fuses output head GEMM + log_softmax).
// NOTE: tcgen05 unusable — harness ptxas targets sm_103 (no 'a').
// N=100000, E=1600000, D=64.
// State invariant: g_cnt and g_flag are zero at entry to each kernel_launch
// (zero-init at load; scatter_kernel re-zeroes them for the next replay).
// Row N of g_xh/g_h1 is a permanent zero row used to pad gather batches.

#define MAXN 100000
#define MAXE 1600000
#define D 64

__device__ int                g_cnt[MAXN];
__device__ int                g_ptr[MAXN + 1];
__device__ int                g_cur[MAXN];
__device__ unsigned long long g_flag[128];
__device__ int                g_csr[MAXE];
__device__ __half             g_mean[MAXN * D];        // fp16 mean
__device__ __half             g_xh[(MAXN + 1) * D];    // fp16 x + zero row N
__device__ __half             g_h1[(MAXN + 1) * D];    // fp16 h1 + zero row N

// ---------------- small helpers ----------------
__device__ __forceinline__ void st4h(__half* p, float x, float y, float z, float w) {
    __half2 h0 = __floats2half2_rn(x, y);
    __half2 h1 = __floats2half2_rn(z, w);
    uint2 u;
    u.x = *reinterpret_cast<unsigned*>(&h0);
    u.y = *reinterpret_cast<unsigned*>(&h1);
    *reinterpret_cast<uint2*>(p) = u;
}
__device__ __forceinline__ uint4 pack8h(float4 f0, float4 f1) {
    __half2 h0 = __floats2half2_rn(f0.x, f0.y);
    __half2 h1 = __floats2half2_rn(f0.z, f0.w);
    __half2 h2 = __floats2half2_rn(f1.x, f1.y);
    __half2 h3 = __floats2half2_rn(f1.z, f1.w);
    uint4 u;
    u.x = *reinterpret_cast<unsigned*>(&h0);
    u.y = *reinterpret_cast<unsigned*>(&h1);
    u.z = *reinterpret_cast<unsigned*>(&h2);
    u.w = *reinterpret_cast<unsigned*>(&h3);
    return u;
}
__device__ __forceinline__ __half2 u2h2(unsigned v) {
    return *reinterpret_cast<const __half2*>(&v);
}
__device__ __forceinline__ uint32_t smem_u32(const void* p) {
    uint32_t a;
    asm("{ .reg .u64 t; cvta.to.shared.u64 t, %1; cvt.u32.u64 %0, t; }"
        : "=r"(a) : "l"(p));
    return a;
}
#define LDSM_X4(r0, r1, r2, r3, addr) \
    asm volatile("ldmatrix.sync.aligned.m8n8.x4.shared.b16 {%0,%1,%2,%3}, [%4];" \
                 : "=r"(r0), "=r"(r1), "=r"(r2), "=r"(r3) : "r"(addr))
__device__ __forceinline__ void mma16816(float* d, uint32_t a0, uint32_t a1,
                                         uint32_t a2, uint32_t a3,
                                         uint32_t b0, uint32_t b1) {
    asm volatile("mma.sync.aligned.m16n8k16.row.col.f32.f16.f16.f32 "
                 "{%0,%1,%2,%3}, {%4,%5,%6,%7}, {%8,%9}, {%0,%1,%2,%3};"
                 : "+f"(d[0]), "+f"(d[1]), "+f"(d[2]), "+f"(d[3])
                 : "r"(a0), "r"(a1), "r"(a2), "r"(a3), "r"(b0), "r"(b1));
}

__device__ __forceinline__ int detect_is64_block(const int* ei32) {
    __shared__ int s_is64;
    if (threadIdx.x == 0) {
        int az = 1;
#pragma unroll
        for (int t = 0; t < 8; t++) az &= (ei32[2 * t + 1] == 0);
        s_is64 = az;
    }
    __syncthreads();
    return s_is64;
}

// ---------------- CSR build (4 edges per thread) ----------------
__global__ void hist_kernel(const void* __restrict__ ei, int* __restrict__ cnt,
                            const float* __restrict__ x, __half* __restrict__ xh,
                            int nquads, int E) {
    const int is64 = detect_is64_block((const int*)ei);
    const int gid = blockIdx.x * blockDim.x + threadIdx.x;
    const int stride = gridDim.x * blockDim.x;
    for (int i = gid; i < nquads; i += stride) {
        float4 v = reinterpret_cast<const float4*>(x)[i];
        st4h(xh + (size_t)i * 4, v.x, v.y, v.z, v.w);
    }
    const int e0 = gid * 4;
    if (e0 >= E) return;
    if (e0 + 3 < E) {
        int d0, d1, d2, d3;
        if (is64) {
            const longlong2* p = (const longlong2*)((const long long*)ei + E + e0);
            longlong2 a = p[0], b = p[1];
            d0 = (int)a.x; d1 = (int)a.y; d2 = (int)b.x; d3 = (int)b.y;
        } else {
            int4 a = *(const int4*)((const int*)ei + E + e0);
            d0 = a.x; d1 = a.y; d2 = a.z; d3 = a.w;
        }
        atomicAdd(&cnt[d0], 1);
        atomicAdd(&cnt[d1], 1);
        atomicAdd(&cnt[d2], 1);
        atomicAdd(&cnt[d3], 1);
    } else {
        for (int e = e0; e < E; e++) {
            int d = is64 ? (int)((const long long*)ei)[(long long)E + e]
                         : ((const int*)ei)[(long long)E + e];
            atomicAdd(&cnt[d], 1);
        }
    }
}

__global__ void scan_kernel(const int* __restrict__ cnt, int* __restrict__ ptr,
                            int* __restrict__ cur, unsigned long long* __restrict__ flag,
                            int N, int E) {
    __shared__ int ssum[256];
    const int tid = threadIdx.x;
    const int b = blockIdx.x;
    const int base = b * 1024 + tid * 4;

    int v0 = (base + 0 < N) ? cnt[base + 0] : 0;
    int v1 = (base + 1 < N) ? cnt[base + 1] : 0;
    int v2 = (base + 2 < N) ? cnt[base + 2] : 0;
    int v3 = (base + 3 < N) ? cnt[base + 3] : 0;
    int s = v0 + v1 + v2 + v3;
    ssum[tid] = s;
    __syncthreads();
    for (int st = 1; st < 256; st <<= 1) {
        int t = (tid >= st) ? ssum[tid - st] : 0;
        __syncthreads();
        ssum[tid] += t;
        __syncthreads();
    }
    const int my_incl = ssum[tid];
    const int total = ssum[255];

    if (tid == 0)
        atomicExch(&flag[b], (((unsigned long long)(unsigned)total) << 1) | 1ull);

    int agg = 0;
    if (tid < b) {
        unsigned long long f;
        do { f = atomicAdd(&flag[tid], 0ull); } while (!(f & 1ull));
        agg = (int)(f >> 1);
    }
    __syncthreads();
    ssum[tid] = agg;
    __syncthreads();
    for (int st = 128; st; st >>= 1) {
        if (tid < st) ssum[tid] += ssum[tid + st];
        __syncthreads();
    }
    const int prev = ssum[0];

    int off = prev + my_incl - s;
    if (base + 0 < N) { ptr[base + 0] = off; cur[base + 0] = off; }  off += v0;
    if (base + 1 < N) { ptr[base + 1] = off; cur[base + 1] = off; }  off += v1;
    if (base + 2 < N) { ptr[base + 2] = off; cur[base + 2] = off; }  off += v2;
    if (base + 3 < N) { ptr[base + 3] = off; cur[base + 3] = off; }
    if (b == 0 && tid == 0) ptr[N] = E;
}

__global__ void scatter_kernel(const void* __restrict__ ei, int* __restrict__ cur,
                               int* __restrict__ csr, int* __restrict__ cnt,
                               unsigned long long* __restrict__ flag, int N, int E) {
    const int is64 = detect_is64_block((const int*)ei);
    const int gid = blockIdx.x * blockDim.x + threadIdx.x;
    if (gid < 128) flag[gid] = 0ull;
    if (gid < N) cnt[gid] = 0;
    const int e0 = gid * 4;
    if (e0 >= E) return;
    if (e0 + 3 < E) {
        int s0, s1, s2, s3, d0, d1, d2, d3;
        if (is64) {
            const longlong2* ps = (const longlong2*)((const long long*)ei + e0);
            const longlong2* pd = (const longlong2*)((const long long*)ei + E + e0);
            longlong2 a = ps[0], b = ps[1], c = pd[0], d = pd[1];
            s0 = (int)a.x; s1 = (int)a.y; s2 = (int)b.x; s3 = (int)b.y;
            d0 = (int)c.x; d1 = (int)c.y; d2 = (int)d.x; d3 = (int)d.y;
        } else {
            int4 a = *(const int4*)((const int*)ei + e0);
            int4 c = *(const int4*)((const int*)ei + E + e0);
            s0 = a.x; s1 = a.y; s2 = a.z; s3 = a.w;
            d0 = c.x; d1 = c.y; d2 = c.z; d3 = c.w;
        }
        csr[atomicAdd(&cur[d0], 1)] = s0;
        csr[atomicAdd(&cur[d1], 1)] = s1;
        csr[atomicAdd(&cur[d2], 1)] = s2;
        csr[atomicAdd(&cur[d3], 1)] = s3;
    } else {
        for (int e = e0; e < E; e++) {
            int s, d;
            if (is64) {
                s = (int)((const long long*)ei)[e];
                d = (int)((const long long*)ei)[(long long)E + e];
            } else {
                s = ((const int*)ei)[e];
                d = ((const int*)ei)[(long long)E + e];
            }
            csr[atomicAdd(&cur[d], 1)] = s;
        }
    }
}

// ---------------- gather + mean (2 nodes/group, dual stream, MLP-16) ---------
// Lane q of each 8-lane group owns halves [8q, 8q+8) = 16B of the feature row.
// Group handles nodes n0=2g, n1=2g+1. Each iteration issues 8 predicated
// LDG.128 for each node's current batch (exhausted slots -> zero row N).
// No separate tail. feat has a zero row at index N.
__global__ void __launch_bounds__(256) gather_mean(
    const __half* __restrict__ feat, const int* __restrict__ ptr,
    const int* __restrict__ csr, __half* __restrict__ mean, int N, int E)
{
    const int gid = blockIdx.x * 256 + threadIdx.x;
    const int g = gid >> 3;
    const int q = gid & 7;
    const unsigned gmask = 0xFFu << (threadIdx.x & 24);

    const int n0 = 2 * g, n1 = n0 + 1;
    int rs0 = 0, re0 = 0, re1 = 0;
    if (n0 < N) {
        rs0 = ptr[n0];
        re0 = ptr[n0 + 1];
        re1 = (n1 < N) ? ptr[n1 + 1] : re0;
    }
    const int d0 = re0 - rs0, d1 = re1 - re0;
    const int it0 = (d0 + 7) >> 3, it1 = (d1 + 7) >> 3;
    const int iters = max(it0, it1);

    __half2 c0 = __floats2half2_rn(0.f, 0.f), c1 = c0, c2 = c0, c3 = c0;
    __half2 e0a = c0, e1a = c0, e2a = c0, e3a = c0;
    const __half* fq = feat + q * 8;
    const int elim = E - 1;

    for (int it = 0; it < iters; it++) {
        const int b0 = rs0 + (it << 3);
        const int b1 = re0 + (it << 3);
        int i0 = csr[min(b0 + q, elim)];
        int i1 = csr[min(b1 + q, elim)];
        // per-slot source indices (invalid -> zero row N)
        int a0 = (b0 + 0 < re0) ? __shfl_sync(gmask, i0, 0, 8) : N;
        int a1 = (b0 + 1 < re0) ? __shfl_sync(gmask, i0, 1, 8) : N;
        int a2 = (b0 + 2 < re0) ? __shfl_sync(gmask, i0, 2, 8) : N;
        int a3 = (b0 + 3 < re0) ? __shfl_sync(gmask, i0, 3, 8) : N;
        int a4 = (b0 + 4 < re0) ? __shfl_sync(gmask, i0, 4, 8) : N;
        int a5 = (b0 + 5 < re0) ? __shfl_sync(gmask, i0, 5, 8) : N;
        int a6 = (b0 + 6 < re0) ? __shfl_sync(gmask, i0, 6, 8) : N;
        int a7 = (b0 + 7 < re0) ? __shfl_sync(gmask, i0, 7, 8) : N;
        int b0i = (b1 + 0 < re1) ? __shfl_sync(gmask, i1, 0, 8) : N;
        int b1i = (b1 + 1 < re1) ? __shfl_sync(gmask, i1, 1, 8) : N;
        int b2i = (b1 + 2 < re1) ? __shfl_sync(gmask, i1, 2, 8) : N;
        int b3i = (b1 + 3 < re1) ? __shfl_sync(gmask, i1, 3, 8) : N;
        int b4i = (b1 + 4 < re1) ? __shfl_sync(gmask, i1, 4, 8) : N;
        int b5i = (b1 + 5 < re1) ? __shfl_sync(gmask, i1, 5, 8) : N;
        int b6i = (b1 + 6 < re1) ? __shfl_sync(gmask, i1, 6, 8) : N;
        int b7i = (b1 + 7 < re1) ? __shfl_sync(gmask, i1, 7, 8) : N;
        // 16 loads in flight
        uint4 v0 = *(const uint4*)(fq + (size_t)a0 * D);
        uint4 v1 = *(const uint4*)(fq + (size_t)a1 * D);
        uint4 v2 = *(const uint4*)(fq + (size_t)a2 * D);
        uint4 v3 = *(const uint4*)(fq + (size_t)a3 * D);
        uint4 v4 = *(const uint4*)(fq + (size_t)a4 * D);
        uint4 v5 = *(const uint4*)(fq + (size_t)a5 * D);
        uint4 v6 = *(const uint4*)(fq + (size_t)a6 * D);
        uint4 v7 = *(const uint4*)(fq + (size_t)a7 * D);
        uint4 w0 = *(const uint4*)(fq + (size_t)b0i * D);
        uint4 w1 = *(const uint4*)(fq + (size_t)b1i * D);
        uint4 w2 = *(const uint4*)(fq + (size_t)b2i * D);
        uint4 w3 = *(const uint4*)(fq + (size_t)b3i * D);
        uint4 w4 = *(const uint4*)(fq + (size_t)b4i * D);
        uint4 w5 = *(const uint4*)(fq + (size_t)b5i * D);
        uint4 w6 = *(const uint4*)(fq + (size_t)b6i * D);
        uint4 w7 = *(const uint4*)(fq + (size_t)b7i * D);
        c0 = __hadd2(c0, u2h2(v0.x)); c1 = __hadd2(c1, u2h2(v0.y));
        c2 = __hadd2(c2, u2h2(v0.z)); c3 = __hadd2(c3, u2h2(v0.w));
        c0 = __hadd2(c0, u2h2(v1.x)); c1 = __hadd2(c1, u2h2(v1.y));
        c2 = __hadd2(c2, u2h2(v1.z)); c3 = __hadd2(c3, u2h2(v1.w));
        c0 = __hadd2(c0, u2h2(v2.x)); c1 = __hadd2(c1, u2h2(v2.y));
        c2 = __hadd2(c2, u2h2(v2.z)); c3 = __hadd2(c3, u2h2(v2.w));
        c0 = __hadd2(c0, u2h2(v3.x)); c1 = __hadd2(c1, u2h2(v3.y));
        c2 = __hadd2(c2, u2h2(v3.z)); c3 = __hadd2(c3, u2h2(v3.w));
        c0 = __hadd2(c0, u2h2(v4.x)); c1 = __hadd2(c1, u2h2(v4.y));
        c2 = __hadd2(c2, u2h2(v4.z)); c3 = __hadd2(c3, u2h2(v4.w));
        c0 = __hadd2(c0, u2h2(v5.x)); c1 = __hadd2(c1, u2h2(v5.y));
        c2 = __hadd2(c2, u2h2(v5.z)); c3 = __hadd2(c3, u2h2(v5.w));
        c0 = __hadd2(c0, u2h2(v6.x)); c1 = __hadd2(c1, u2h2(v6.y));
        c2 = __hadd2(c2, u2h2(v6.z)); c3 = __hadd2(c3, u2h2(v6.w));
        c0 = __hadd2(c0, u2h2(v7.x)); c1 = __hadd2(c1, u2h2(v7.y));
        c2 = __hadd2(c2, u2h2(v7.z)); c3 = __hadd2(c3, u2h2(v7.w));
        e0a = __hadd2(e0a, u2h2(w0.x)); e1a = __hadd2(e1a, u2h2(w0.y));
        e2a = __hadd2(e2a, u2h2(w0.z)); e3a = __hadd2(e3a, u2h2(w0.w));
        e0a = __hadd2(e0a, u2h2(w1.x)); e1a = __hadd2(e1a, u2h2(w1.y));
        e2a = __hadd2(e2a, u2h2(w1.z)); e3a = __hadd2(e3a, u2h2(w1.w));
        e0a = __hadd2(e0a, u2h2(w2.x)); e1a = __hadd2(e1a, u2h2(w2.y));
        e2a = __hadd2(e2a, u2h2(w2.z)); e3a = __hadd2(e3a, u2h2(w2.w));
        e0a = __hadd2(e0a, u2h2(w3.x)); e1a = __hadd2(e1a, u2h2(w3.y));
        e2a = __hadd2(e2a, u2h2(w3.z)); e3a = __hadd2(e3a, u2h2(w3.w));
        e0a = __hadd2(e0a, u2h2(w4.x)); e1a = __hadd2(e1a, u2h2(w4.y));
        e2a = __hadd2(e2a, u2h2(w4.z)); e3a = __hadd2(e3a, u2h2(w4.w));
        e0a = __hadd2(e0a, u2h2(w5.x)); e1a = __hadd2(e1a, u2h2(w5.y));
        e2a = __hadd2(e2a, u2h2(w5.z)); e3a = __hadd2(e3a, u2h2(w5.w));
        e0a = __hadd2(e0a, u2h2(w6.x)); e1a = __hadd2(e1a, u2h2(w6.y));
        e2a = __hadd2(e2a, u2h2(w6.z)); e3a = __hadd2(e3a, u2h2(w6.w));
        e0a = __hadd2(e0a, u2h2(w7.x)); e1a = __hadd2(e1a, u2h2(w7.y));
        e2a = __hadd2(e2a, u2h2(w7.z)); e3a = __hadd2(e3a, u2h2(w7.w));
    }

    if (n0 < N) {
        float2 f0 = __half22float2(c0);
        float2 f1 = __half22float2(c1);
        float2 f2 = __half22float2(c2);
        float2 f3 = __half22float2(c3);
        const float iv = 1.0f / fmaxf((float)d0, 1.0f);
        *(uint4*)(mean + (size_t)n0 * D + q * 8) =
            pack8h(make_float4(f0.x * iv, f0.y * iv, f1.x * iv, f1.y * iv),
                   make_float4(f2.x * iv, f2.y * iv, f3.x * iv, f3.y * iv));
    }
    if (n1 < N) {
        float2 f0 = __half22float2(e0a);
        float2 f1 = __half22float2(e1a);
        float2 f2 = __half22float2(e2a);
        float2 f3 = __half22float2(e3a);
        const float iv = 1.0f / fmaxf((float)d1, 1.0f);
        *(uint4*)(mean + (size_t)n1 * D + q * 8) =
            pack8h(make_float4(f0.x * iv, f0.y * iv, f1.x * iv, f1.y * iv),
                   make_float4(f2.x * iv, f2.y * iv, f3.x * iv, f3.y * iv));
    }
}

// ---------------- HMMA SAGE transform (unchanged) ----------------
template<bool HEAD>
__global__ void __launch_bounds__(256) hmma_transform(
    const __half* __restrict__ mean, const __half* __restrict__ xsrc,
    const float* __restrict__ Wl, const float* __restrict__ bl,
    const float* __restrict__ Wr, const float* __restrict__ Wo,
    const float* __restrict__ bo, void* __restrict__ outp, int N)
{
    extern __shared__ char smem[];
    char* SA = smem;                               // 32768 B
    char* SB = smem + 32768;                       // 16384 B
    float* bls = (float*)(smem + 49152);
    float* bos = (float*)(smem + 49408);

    const int tid = threadIdx.x;
    const int w = tid >> 5, lane = tid & 31;
    const int base = blockIdx.x * 128;

    if (tid < 64) { bls[tid] = bl[tid]; if (HEAD) bos[tid] = bo[tid]; }

    for (int i = tid; i < 2048; i += 256) {
        const int row = i >> 4, c = i & 15;
        const int n = base + row;
        uint4 val = make_uint4(0u, 0u, 0u, 0u);
        if (n < N) {
            val = (c < 8) ? *(const uint4*)(mean + (size_t)n * D + c * 8)
                          : *(const uint4*)(xsrc + (size_t)n * D + (c - 8) * 8);
        }
        *(uint4*)(SA + row * 256 + ((c ^ (row & 7)) << 4)) = val;
    }
    for (int i = tid; i < 1024; i += 256) {
        const int row = i >> 4, c = i & 15;
        const float* src = (c < 8) ? (Wl + row * D + c * 8)
                                   : (Wr + row * D + (c - 8) * 8);
        float4 f0 = *(const float4*)src;
        float4 f1 = *(const float4*)(src + 4);
        *(uint4*)(SB + row * 256 + ((c ^ (row & 7)) << 4)) = pack8h(f0, f1);
    }
    __syncthreads();

    float acc[8][4];
#pragma unroll
    for (int t = 0; t < 8; t++)
        acc[t][0] = acc[t][1] = acc[t][2] = acc[t][3] = 0.f;

    const int arow = 16 * w + (lane & 15);
    const int ac = lane >> 4;
    const int bn = (lane & 7) + ((lane >> 4) << 3);
    const int bc = (lane >> 3) & 1;

#pragma unroll
    for (int t = 0; t < 8; t++) {
        uint32_t a0, a1, a2, a3;
        uint32_t aaddr = smem_u32(SA + arow * 256 + (((2 * t + ac) ^ (arow & 7)) << 4));
        LDSM_X4(a0, a1, a2, a3, aaddr);
#pragma unroll
        for (int p = 0; p < 4; p++) {
            const int nn = bn + 16 * p;
            uint32_t baddr = smem_u32(SB + nn * 256 + (((2 * t + bc) ^ (nn & 7)) << 4));
            uint32_t b0, b1, b2, b3;
            LDSM_X4(b0, b1, b2, b3, baddr);
            mma16816(acc[2 * p + 0], a0, a1, a2, a3, b0, b1);
            mma16816(acc[2 * p + 1], a0, a1, a2, a3, b2, b3);
        }
    }
    __syncthreads();

    const int r0 = 16 * w + (lane >> 2);
    const int r1 = r0 + 8;
    const int cb = 2 * (lane & 3);
#pragma unroll
    for (int t = 0; t < 8; t++) {
        const int c = 8 * t + cb;
        acc[t][0] = fmaxf(acc[t][0] + bls[c],     0.f);
        acc[t][1] = fmaxf(acc[t][1] + bls[c + 1], 0.f);
        acc[t][2] = fmaxf(acc[t][2] + bls[c],     0.f);
        acc[t][3] = fmaxf(acc[t][3] + bls[c + 1], 0.f);
    }

    if (!HEAD) {
#pragma unroll
        for (int t = 0; t < 8; t++) {
            const int c = 8 * t + cb;
            *(__half2*)(SA + r0 * 144 + c * 2) = __floats2half2_rn(acc[t][0], acc[t][1]);
            *(__half2*)(SA + r1 * 144 + c * 2) = __floats2half2_rn(acc[t][2], acc[t][3]);
        }
        __syncthreads();
        for (int i = tid; i < 1024; i += 256) {
            const int row = i >> 3, c8 = i & 7;
            if (base + row < N)
                *(uint4*)((__half*)outp + (size_t)(base + row) * D + c8 * 8) =
                    *(uint4*)(SA + row * 144 + c8 * 16);
        }
    } else {
#pragma unroll
        for (int t = 0; t < 8; t++) {
            *(__half2*)(SA + r0 * 128 + ((t ^ (r0 & 7)) << 4) + cb * 2) =
                __floats2half2_rn(acc[t][0], acc[t][1]);
            *(__half2*)(SA + r1 * 128 + ((t ^ (r1 & 7)) << 4) + cb * 2) =
                __floats2half2_rn(acc[t][2], acc[t][3]);
        }
        for (int i = tid; i < 512; i += 256) {
            const int row = i >> 3, c = i & 7;
            float4 f0 = *(const float4*)(Wo + row * D + c * 8);
            float4 f1 = *(const float4*)(Wo + row * D + c * 8 + 4);
            *(uint4*)(SB + row * 128 + ((c ^ (row & 7)) << 4)) = pack8h(f0, f1);
        }
        __syncthreads();

        float ac2[8][4];
#pragma unroll
        for (int t = 0; t < 8; t++)
            ac2[t][0] = ac2[t][1] = ac2[t][2] = ac2[t][3] = 0.f;
#pragma unroll
        for (int t = 0; t < 4; t++) {
            uint32_t a0, a1, a2, a3;
            uint32_t aaddr = smem_u32(SA + arow * 128 + (((2 * t + ac) ^ (arow & 7)) << 4));
            LDSM_X4(a0, a1, a2, a3, aaddr);
#pragma unroll
            for (int p = 0; p < 4; p++) {
                const int nn = bn + 16 * p;
                uint32_t baddr = smem_u32(SB + nn * 128 + (((2 * t + bc) ^ (nn & 7)) << 4));
                uint32_t b0, b1, b2, b3;
                LDSM_X4(b0, b1, b2, b3, baddr);
                mma16816(ac2[2 * p + 0], a0, a1, a2, a3, b0, b1);
                mma16816(ac2[2 * p + 1], a0, a1, a2, a3, b2, b3);
            }
        }
        __syncthreads();

#pragma unroll
        for (int t = 0; t < 8; t++) {
            const int c = 8 * t + cb;
            *(float2*)(smem + r0 * 264 + c * 4) =
                make_float2(ac2[t][0] + bos[c], ac2[t][1] + bos[c + 1]);
            *(float2*)(smem + r1 * 264 + c * 4) =
                make_float2(ac2[t][2] + bos[c], ac2[t][3] + bos[c + 1]);
        }
        __syncthreads();

        if (tid < 128) {
            const float* lr = (const float*)(smem + tid * 264);
            float mx = -1e30f;
#pragma unroll
            for (int c = 0; c < 64; c++) mx = fmaxf(mx, lr[c]);
            float sm = 0.f;
#pragma unroll
            for (int c = 0; c < 64; c++) sm += expf(lr[c] - mx);
            const float lse = mx + logf(sm);
            const int n = base + tid;
            if (n < N) {
                float* op = (float*)outp + (size_t)n * D;
#pragma unroll
                for (int c = 0; c < 64; c += 4) {
                    float4 r = make_float4(lr[c] - lse, lr[c + 1] - lse,
                                           lr[c + 2] - lse, lr[c + 3] - lse);
                    *(float4*)(op + c) = r;
                }
            }
        }
    }
}

// ---------------------------------------------------------------------------
extern "C" void kernel_launch(void* const* d_in, const int* in_sizes, int n_in,
                              void* d_out, int out_size) {
    const float* x    = (const float*)d_in[0];
    const void*  ei   = d_in[1];
    const float* W1l  = (const float*)d_in[2];
    const float* b1l  = (const float*)d_in[3];
    const float* W1r  = (const float*)d_in[4];
    const float* W2l  = (const float*)d_in[5];
    const float* b2l  = (const float*)d_in[6];
    const float* W2r  = (const float*)d_in[7];
    const float* Wout = (const float*)d_in[8];
    const float* bout = (const float*)d_in[9];

    const int N = in_sizes[0] / D;
    const int E = in_sizes[1] / 2;

    int*   cnt;  cudaGetSymbolAddress((void**)&cnt,  g_cnt);
    int*   ptr;  cudaGetSymbolAddress((void**)&ptr,  g_ptr);
    int*   cur;  cudaGetSymbolAddress((void**)&cur,  g_cur);
    unsigned long long* flag; cudaGetSymbolAddress((void**)&flag, g_flag);
    int*   csr;  cudaGetSymbolAddress((void**)&csr,  g_csr);
    __half* mean; cudaGetSymbolAddress((void**)&mean, g_mean);
    __half* xh;  cudaGetSymbolAddress((void**)&xh,   g_xh);
    __half* h1;  cudaGetSymbolAddress((void**)&h1,   g_h1);

    const int SMEM_MMA = 49152 + 512;

    cudaStreamCaptureStatus cs = cudaStreamCaptureStatusNone;
    cudaStreamIsCapturing(0, &cs);
    if (cs == cudaStreamCaptureStatusNone) {
        cudaFuncSetAttribute(hmma_transform<false>,
                             cudaFuncAttributeMaxDynamicSharedMemorySize, SMEM_MMA);
        cudaFuncSetAttribute(hmma_transform<true>,
                             cudaFuncAttributeMaxDynamicSharedMemorySize, SMEM_MMA);
    }

    const int nb = (N + 1023) / 1024;
    const int e4blocks = ((E + 3) / 4 + 255) / 256;     // 4 edges/thread
    const int ngroups = (N + 1) / 2;                    // 2 nodes/group
    const int gblocks = (ngroups * 8 + 255) / 256;      // 8 lanes/group
    const int mblocks = (N + 127) / 128;

    // CSR build: [0] hist + x->fp16, [1] scan, [2] scatter(+state reset)
    hist_kernel<<<e4blocks, 256>>>(ei, cnt, x, xh, N * D / 4, E);
    scan_kernel<<<nb, 256>>>(cnt, ptr, cur, flag, N, E);
    scatter_kernel<<<e4blocks, 256>>>(ei, cur, csr, cnt, flag, N, E);

    // Layer 1: [3] gather (profiled), [4] HMMA transform -> fp16 h1
    gather_mean<<<gblocks, 256>>>(xh, ptr, csr, mean, N, E);
    hmma_transform<false><<<mblocks, 256, SMEM_MMA>>>(
        mean, xh, W1l, b1l, W1r, nullptr, nullptr, h1, N);
    // Layer 2 + head: [5] gather, [6] HMMA transform + head + log_softmax
    gather_mean<<<gblocks, 256>>>(h1, ptr, csr, mean, N, E);
    hmma_transform<true><<<mblocks, 256, SMEM_MMA>>>(
        mean, h1, W2l, b2l, W2r, Wout, bout, (float*)d_out, N);
}

// round 14
// speedup vs baseline: 1.1627x; 1.1627x over previous
#include <cuda_runtime.h>
#include <cuda_fp16.h>
#include <math.h>
#include <stdint.h>

// GraphSAGE encoder:
//   CSR build (3 launches, 4 edges/thread) -> fp16 gather/mean (8 lanes/node,
//   LDG.128, MLP-8 loads-first batches, csr-index software pipelining,
//   fp16 accumulation) -> HMMA transform
//   (layer 2 fuses output head GEMM + log_softmax).
// NOTE: tcgen05 unusable — harness ptxas targets sm_103 (no 'a').
// N=100000, E=1600000, D=64.
// State invariant: g_cnt and g_flag are zero at entry to each kernel_launch
// (zero-init at load; scatter_kernel re-zeroes them for the next replay).

#define MAXN 100000
#define MAXE 1600000
#define D 64

__device__ int                g_cnt[MAXN];
__device__ int                g_ptr[MAXN + 1];
__device__ int                g_cur[MAXN];
__device__ unsigned long long g_flag[128];
__device__ int                g_csr[MAXE];
__device__ __half             g_mean[MAXN * D]; // fp16 mean (gather output)
__device__ __half             g_xh[MAXN * D];   // fp16 copy of x
__device__ __half             g_h1[MAXN * D];   // layer-1 activations (fp16)
__device__ __align__(16) __half g_zero[64];     // stays zero (never written)

// ---------------- small helpers ----------------
__device__ __forceinline__ void st4h(__half* p, float x, float y, float z, float w) {
    __half2 h0 = __floats2half2_rn(x, y);
    __half2 h1 = __floats2half2_rn(z, w);
    uint2 u;
    u.x = *reinterpret_cast<unsigned*>(&h0);
    u.y = *reinterpret_cast<unsigned*>(&h1);
    *reinterpret_cast<uint2*>(p) = u;
}
__device__ __forceinline__ uint4 pack8h(float4 f0, float4 f1) {
    __half2 h0 = __floats2half2_rn(f0.x, f0.y);
    __half2 h1 = __floats2half2_rn(f0.z, f0.w);
    __half2 h2 = __floats2half2_rn(f1.x, f1.y);
    __half2 h3 = __floats2half2_rn(f1.z, f1.w);
    uint4 u;
    u.x = *reinterpret_cast<unsigned*>(&h0);
    u.y = *reinterpret_cast<unsigned*>(&h1);
    u.z = *reinterpret_cast<unsigned*>(&h2);
    u.w = *reinterpret_cast<unsigned*>(&h3);
    return u;
}
__device__ __forceinline__ __half2 u2h2(unsigned v) {
    return *reinterpret_cast<const __half2*>(&v);
}
__device__ __forceinline__ uint32_t smem_u32(const void* p) {
    uint32_t a;
    asm("{ .reg .u64 t; cvta.to.shared.u64 t, %1; cvt.u32.u64 %0, t; }"
        : "=r"(a) : "l"(p));
    return a;
}
#define LDSM_X4(r0, r1, r2, r3, addr) \
    asm volatile("ldmatrix.sync.aligned.m8n8.x4.shared.b16 {%0,%1,%2,%3}, [%4];" \
                 : "=r"(r0), "=r"(r1), "=r"(r2), "=r"(r3) : "r"(addr))
__device__ __forceinline__ void mma16816(float* d, uint32_t a0, uint32_t a1,
                                         uint32_t a2, uint32_t a3,
                                         uint32_t b0, uint32_t b1) {
    asm volatile("mma.sync.aligned.m16n8k16.row.col.f32.f16.f16.f32 "
                 "{%0,%1,%2,%3}, {%4,%5,%6,%7}, {%8,%9}, {%0,%1,%2,%3};"
                 : "+f"(d[0]), "+f"(d[1]), "+f"(d[2]), "+f"(d[3])
                 : "r"(a0), "r"(a1), "r"(a2), "r"(a3), "r"(b0), "r"(b1));
}

__device__ __forceinline__ int detect_is64_block(const int* ei32) {
    __shared__ int s_is64;
    if (threadIdx.x == 0) {
        int az = 1;
#pragma unroll
        for (int t = 0; t < 8; t++) az &= (ei32[2 * t + 1] == 0);
        s_is64 = az;
    }
    __syncthreads();
    return s_is64;
}

// ---------------- CSR build (4 edges per thread) ----------------
__global__ void hist_kernel(const void* __restrict__ ei, int* __restrict__ cnt,
                            const float* __restrict__ x, __half* __restrict__ xh,
                            int nquads, int E) {
    const int is64 = detect_is64_block((const int*)ei);
    const int gid = blockIdx.x * blockDim.x + threadIdx.x;
    const int stride = gridDim.x * blockDim.x;
    for (int i = gid; i < nquads; i += stride) {
        float4 v = reinterpret_cast<const float4*>(x)[i];
        st4h(xh + (size_t)i * 4, v.x, v.y, v.z, v.w);
    }
    const int e0 = gid * 4;
    if (e0 >= E) return;
    if (e0 + 3 < E) {
        int d0, d1, d2, d3;
        if (is64) {
            const longlong2* p = (const longlong2*)((const long long*)ei + E + e0);
            longlong2 a = p[0], b = p[1];
            d0 = (int)a.x; d1 = (int)a.y; d2 = (int)b.x; d3 = (int)b.y;
        } else {
            int4 a = *(const int4*)((const int*)ei + E + e0);
            d0 = a.x; d1 = a.y; d2 = a.z; d3 = a.w;
        }
        atomicAdd(&cnt[d0], 1);
        atomicAdd(&cnt[d1], 1);
        atomicAdd(&cnt[d2], 1);
        atomicAdd(&cnt[d3], 1);
    } else {
        for (int e = e0; e < E; e++) {
            int d = is64 ? (int)((const long long*)ei)[(long long)E + e]
                         : ((const int*)ei)[(long long)E + e];
            atomicAdd(&cnt[d], 1);
        }
    }
}

__global__ void scan_kernel(const int* __restrict__ cnt, int* __restrict__ ptr,
                            int* __restrict__ cur, unsigned long long* __restrict__ flag,
                            int N, int E) {
    __shared__ int ssum[256];
    const int tid = threadIdx.x;
    const int b = blockIdx.x;
    const int base = b * 1024 + tid * 4;

    int v0 = (base + 0 < N) ? cnt[base + 0] : 0;
    int v1 = (base + 1 < N) ? cnt[base + 1] : 0;
    int v2 = (base + 2 < N) ? cnt[base + 2] : 0;
    int v3 = (base + 3 < N) ? cnt[base + 3] : 0;
    int s = v0 + v1 + v2 + v3;
    ssum[tid] = s;
    __syncthreads();
    for (int st = 1; st < 256; st <<= 1) {
        int t = (tid >= st) ? ssum[tid - st] : 0;
        __syncthreads();
        ssum[tid] += t;
        __syncthreads();
    }
    const int my_incl = ssum[tid];
    const int total = ssum[255];

    if (tid == 0)
        atomicExch(&flag[b], (((unsigned long long)(unsigned)total) << 1) | 1ull);

    int agg = 0;
    if (tid < b) {
        unsigned long long f;
        do { f = atomicAdd(&flag[tid], 0ull); } while (!(f & 1ull));
        agg = (int)(f >> 1);
    }
    __syncthreads();
    ssum[tid] = agg;
    __syncthreads();
    for (int st = 128; st; st >>= 1) {
        if (tid < st) ssum[tid] += ssum[tid + st];
        __syncthreads();
    }
    const int prev = ssum[0];

    int off = prev + my_incl - s;
    if (base + 0 < N) { ptr[base + 0] = off; cur[base + 0] = off; }  off += v0;
    if (base + 1 < N) { ptr[base + 1] = off; cur[base + 1] = off; }  off += v1;
    if (base + 2 < N) { ptr[base + 2] = off; cur[base + 2] = off; }  off += v2;
    if (base + 3 < N) { ptr[base + 3] = off; cur[base + 3] = off; }
    if (b == 0 && tid == 0) ptr[N] = E;
}

__global__ void scatter_kernel(const void* __restrict__ ei, int* __restrict__ cur,
                               int* __restrict__ csr, int* __restrict__ cnt,
                               unsigned long long* __restrict__ flag, int N, int E) {
    const int is64 = detect_is64_block((const int*)ei);
    const int gid = blockIdx.x * blockDim.x + threadIdx.x;
    if (gid < 128) flag[gid] = 0ull;
    if (gid < N) cnt[gid] = 0;
    const int e0 = gid * 4;
    if (e0 >= E) return;
    if (e0 + 3 < E) {
        int s0, s1, s2, s3, d0, d1, d2, d3;
        if (is64) {
            const longlong2* ps = (const longlong2*)((const long long*)ei + e0);
            const longlong2* pd = (const longlong2*)((const long long*)ei + E + e0);
            longlong2 a = ps[0], b = ps[1], c = pd[0], d = pd[1];
            s0 = (int)a.x; s1 = (int)a.y; s2 = (int)b.x; s3 = (int)b.y;
            d0 = (int)c.x; d1 = (int)c.y; d2 = (int)d.x; d3 = (int)d.y;
        } else {
            int4 a = *(const int4*)((const int*)ei + e0);
            int4 c = *(const int4*)((const int*)ei + E + e0);
            s0 = a.x; s1 = a.y; s2 = a.z; s3 = a.w;
            d0 = c.x; d1 = c.y; d2 = c.z; d3 = c.w;
        }
        csr[atomicAdd(&cur[d0], 1)] = s0;
        csr[atomicAdd(&cur[d1], 1)] = s1;
        csr[atomicAdd(&cur[d2], 1)] = s2;
        csr[atomicAdd(&cur[d3], 1)] = s3;
    } else {
        for (int e = e0; e < E; e++) {
            int s, d;
            if (is64) {
                s = (int)((const long long*)ei)[e];
                d = (int)((const long long*)ei)[(long long)E + e];
            } else {
                s = ((const int*)ei)[e];
                d = ((const int*)ei)[(long long)E + e];
            }
            csr[atomicAdd(&cur[d], 1)] = s;
        }
    }
}

// ---------------- gather + mean (8 lanes/node, LDG.128, MLP-8, pipelined) ----
// Lane q of each 8-lane group owns halves [8q, 8q+8) = 16B of the feature row.
// Main loop: 8-edge batches, all 8 LDG.128 in flight; the NEXT batch's csr
// indices are prefetched (clamped address, discarded at tail) so the index
// load's L2 latency overlaps the current batch's feature loads.
// Tail: one predicated 8-slot batch (zero-row fill).
__global__ void __launch_bounds__(256) gather_mean(
    const __half* __restrict__ feat, const int* __restrict__ ptr,
    const int* __restrict__ csr, __half* __restrict__ mean, int N, int E)
{
    const int gid = blockIdx.x * 256 + threadIdx.x;
    const int n = gid >> 3;
    const int q = gid & 7;
    const unsigned gmask = 0xFFu << (threadIdx.x & 24);

    int rs = 0, re = 0;
    if (n < N) { rs = ptr[n]; re = ptr[n + 1]; }

    __half2 c0 = __floats2half2_rn(0.f, 0.f), c1 = c0, c2 = c0, c3 = c0;
    const __half* fq = feat + q * 8;
    const __half* zq = g_zero + q * 8;
    const int elim = E - 1;

    int b = rs;
    int idx = (b < re) ? csr[min(b + q, elim)] : 0;   // first batch indices
    // ---- full 8-edge batches, 8 loads in flight + next-index prefetch ----
    for (; b + 8 <= re; b += 8) {
        const int idx_c = idx;
        // prefetch next batch's index (valid address; discarded past tail)
        idx = csr[min(b + 8 + q, elim)];
        int s0 = __shfl_sync(gmask, idx_c, 0, 8);
        int s1 = __shfl_sync(gmask, idx_c, 1, 8);
        int s2 = __shfl_sync(gmask, idx_c, 2, 8);
        int s3 = __shfl_sync(gmask, idx_c, 3, 8);
        int s4 = __shfl_sync(gmask, idx_c, 4, 8);
        int s5 = __shfl_sync(gmask, idx_c, 5, 8);
        int s6 = __shfl_sync(gmask, idx_c, 6, 8);
        int s7 = __shfl_sync(gmask, idx_c, 7, 8);
        uint4 v0 = *(const uint4*)(fq + (size_t)s0 * D);
        uint4 v1 = *(const uint4*)(fq + (size_t)s1 * D);
        uint4 v2 = *(const uint4*)(fq + (size_t)s2 * D);
        uint4 v3 = *(const uint4*)(fq + (size_t)s3 * D);
        uint4 v4 = *(const uint4*)(fq + (size_t)s4 * D);
        uint4 v5 = *(const uint4*)(fq + (size_t)s5 * D);
        uint4 v6 = *(const uint4*)(fq + (size_t)s6 * D);
        uint4 v7 = *(const uint4*)(fq + (size_t)s7 * D);
        c0 = __hadd2(c0, u2h2(v0.x)); c1 = __hadd2(c1, u2h2(v0.y));
        c2 = __hadd2(c2, u2h2(v0.z)); c3 = __hadd2(c3, u2h2(v0.w));
        c0 = __hadd2(c0, u2h2(v1.x)); c1 = __hadd2(c1, u2h2(v1.y));
        c2 = __hadd2(c2, u2h2(v1.z)); c3 = __hadd2(c3, u2h2(v1.w));
        c0 = __hadd2(c0, u2h2(v2.x)); c1 = __hadd2(c1, u2h2(v2.y));
        c2 = __hadd2(c2, u2h2(v2.z)); c3 = __hadd2(c3, u2h2(v2.w));
        c0 = __hadd2(c0, u2h2(v3.x)); c1 = __hadd2(c1, u2h2(v3.y));
        c2 = __hadd2(c2, u2h2(v3.z)); c3 = __hadd2(c3, u2h2(v3.w));
        c0 = __hadd2(c0, u2h2(v4.x)); c1 = __hadd2(c1, u2h2(v4.y));
        c2 = __hadd2(c2, u2h2(v4.z)); c3 = __hadd2(c3, u2h2(v4.w));
        c0 = __hadd2(c0, u2h2(v5.x)); c1 = __hadd2(c1, u2h2(v5.y));
        c2 = __hadd2(c2, u2h2(v5.z)); c3 = __hadd2(c3, u2h2(v5.w));
        c0 = __hadd2(c0, u2h2(v6.x)); c1 = __hadd2(c1, u2h2(v6.y));
        c2 = __hadd2(c2, u2h2(v6.z)); c3 = __hadd2(c3, u2h2(v6.w));
        c0 = __hadd2(c0, u2h2(v7.x)); c1 = __hadd2(c1, u2h2(v7.y));
        c2 = __hadd2(c2, u2h2(v7.z)); c3 = __hadd2(c3, u2h2(v7.w));
    }
    // ---- tail: one predicated 8-slot batch (idx already holds its indices) --
    if (b < re) {
        const int cnt = re - b;
        int s0 = __shfl_sync(gmask, idx, 0, 8);
        int s1 = __shfl_sync(gmask, idx, 1, 8);
        int s2 = __shfl_sync(gmask, idx, 2, 8);
        int s3 = __shfl_sync(gmask, idx, 3, 8);
        int s4 = __shfl_sync(gmask, idx, 4, 8);
        int s5 = __shfl_sync(gmask, idx, 5, 8);
        int s6 = __shfl_sync(gmask, idx, 6, 8);
        int s7 = __shfl_sync(gmask, idx, 7, 8);
        const __half* p0 = (0 < cnt) ? fq + (size_t)s0 * D : zq;
        const __half* p1 = (1 < cnt) ? fq + (size_t)s1 * D : zq;
        const __half* p2 = (2 < cnt) ? fq + (size_t)s2 * D : zq;
        const __half* p3 = (3 < cnt) ? fq + (size_t)s3 * D : zq;
        const __half* p4 = (4 < cnt) ? fq + (size_t)s4 * D : zq;
        const __half* p5 = (5 < cnt) ? fq + (size_t)s5 * D : zq;
        const __half* p6 = (6 < cnt) ? fq + (size_t)s6 * D : zq;
        const __half* p7 = (7 < cnt) ? fq + (size_t)s7 * D : zq;
        uint4 v0 = *(const uint4*)p0;
        uint4 v1 = *(const uint4*)p1;
        uint4 v2 = *(const uint4*)p2;
        uint4 v3 = *(const uint4*)p3;
        uint4 v4 = *(const uint4*)p4;
        uint4 v5 = *(const uint4*)p5;
        uint4 v6 = *(const uint4*)p6;
        uint4 v7 = *(const uint4*)p7;
        c0 = __hadd2(c0, u2h2(v0.x)); c1 = __hadd2(c1, u2h2(v0.y));
        c2 = __hadd2(c2, u2h2(v0.z)); c3 = __hadd2(c3, u2h2(v0.w));
        c0 = __hadd2(c0, u2h2(v1.x)); c1 = __hadd2(c1, u2h2(v1.y));
        c2 = __hadd2(c2, u2h2(v1.z)); c3 = __hadd2(c3, u2h2(v1.w));
        c0 = __hadd2(c0, u2h2(v2.x)); c1 = __hadd2(c1, u2h2(v2.y));
        c2 = __hadd2(c2, u2h2(v2.z)); c3 = __hadd2(c3, u2h2(v2.w));
        c0 = __hadd2(c0, u2h2(v3.x)); c1 = __hadd2(c1, u2h2(v3.y));
        c2 = __hadd2(c2, u2h2(v3.z)); c3 = __hadd2(c3, u2h2(v3.w));
        c0 = __hadd2(c0, u2h2(v4.x)); c1 = __hadd2(c1, u2h2(v4.y));
        c2 = __hadd2(c2, u2h2(v4.z)); c3 = __hadd2(c3, u2h2(v4.w));
        c0 = __hadd2(c0, u2h2(v5.x)); c1 = __hadd2(c1, u2h2(v5.y));
        c2 = __hadd2(c2, u2h2(v5.z)); c3 = __hadd2(c3, u2h2(v5.w));
        c0 = __hadd2(c0, u2h2(v6.x)); c1 = __hadd2(c1, u2h2(v6.y));
        c2 = __hadd2(c2, u2h2(v6.z)); c3 = __hadd2(c3, u2h2(v6.w));
        c0 = __hadd2(c0, u2h2(v7.x)); c1 = __hadd2(c1, u2h2(v7.y));
        c2 = __hadd2(c2, u2h2(v7.z)); c3 = __hadd2(c3, u2h2(v7.w));
    }

    if (n < N) {
        float2 f0 = __half22float2(c0);
        float2 f1 = __half22float2(c1);
        float2 f2 = __half22float2(c2);
        float2 f3 = __half22float2(c3);
        const float invd = 1.0f / fmaxf((float)(re - rs), 1.0f);
        float4 a = make_float4(f0.x * invd, f0.y * invd, f1.x * invd, f1.y * invd);
        float4 bq = make_float4(f2.x * invd, f2.y * invd, f3.x * invd, f3.y * invd);
        *(uint4*)(mean + (size_t)n * D + q * 8) = pack8h(a, bq);
    }
}

// ---------------- HMMA SAGE transform (unchanged) ----------------
template<bool HEAD>
__global__ void __launch_bounds__(256) hmma_transform(
    const __half* __restrict__ mean, const __half* __restrict__ xsrc,
    const float* __restrict__ Wl, const float* __restrict__ bl,
    const float* __restrict__ Wr, const float* __restrict__ Wo,
    const float* __restrict__ bo, void* __restrict__ outp, int N)
{
    extern __shared__ char smem[];
    char* SA = smem;                               // 32768 B
    char* SB = smem + 32768;                       // 16384 B
    float* bls = (float*)(smem + 49152);
    float* bos = (float*)(smem + 49408);

    const int tid = threadIdx.x;
    const int w = tid >> 5, lane = tid & 31;
    const int base = blockIdx.x * 128;

    if (tid < 64) { bls[tid] = bl[tid]; if (HEAD) bos[tid] = bo[tid]; }

    for (int i = tid; i < 2048; i += 256) {
        const int row = i >> 4, c = i & 15;
        const int n = base + row;
        uint4 val = make_uint4(0u, 0u, 0u, 0u);
        if (n < N) {
            val = (c < 8) ? *(const uint4*)(mean + (size_t)n * D + c * 8)
                          : *(const uint4*)(xsrc + (size_t)n * D + (c - 8) * 8);
        }
        *(uint4*)(SA + row * 256 + ((c ^ (row & 7)) << 4)) = val;
    }
    for (int i = tid; i < 1024; i += 256) {
        const int row = i >> 4, c = i & 15;
        const float* src = (c < 8) ? (Wl + row * D + c * 8)
                                   : (Wr + row * D + (c - 8) * 8);
        float4 f0 = *(const float4*)src;
        float4 f1 = *(const float4*)(src + 4);
        *(uint4*)(SB + row * 256 + ((c ^ (row & 7)) << 4)) = pack8h(f0, f1);
    }
    __syncthreads();

    float acc[8][4];
#pragma unroll
    for (int t = 0; t < 8; t++)
        acc[t][0] = acc[t][1] = acc[t][2] = acc[t][3] = 0.f;

    const int arow = 16 * w + (lane & 15);
    const int ac = lane >> 4;
    const int bn = (lane & 7) + ((lane >> 4) << 3);
    const int bc = (lane >> 3) & 1;

#pragma unroll
    for (int t = 0; t < 8; t++) {
        uint32_t a0, a1, a2, a3;
        uint32_t aaddr = smem_u32(SA + arow * 256 + (((2 * t + ac) ^ (arow & 7)) << 4));
        LDSM_X4(a0, a1, a2, a3, aaddr);
#pragma unroll
        for (int p = 0; p < 4; p++) {
            const int nn = bn + 16 * p;
            uint32_t baddr = smem_u32(SB + nn * 256 + (((2 * t + bc) ^ (nn & 7)) << 4));
            uint32_t b0, b1, b2, b3;
            LDSM_X4(b0, b1, b2, b3, baddr);
            mma16816(acc[2 * p + 0], a0, a1, a2, a3, b0, b1);
            mma16816(acc[2 * p + 1], a0, a1, a2, a3, b2, b3);
        }
    }
    __syncthreads();

    const int r0 = 16 * w + (lane >> 2);
    const int r1 = r0 + 8;
    const int cb = 2 * (lane & 3);
#pragma unroll
    for (int t = 0; t < 8; t++) {
        const int c = 8 * t + cb;
        acc[t][0] = fmaxf(acc[t][0] + bls[c],     0.f);
        acc[t][1] = fmaxf(acc[t][1] + bls[c + 1], 0.f);
        acc[t][2] = fmaxf(acc[t][2] + bls[c],     0.f);
        acc[t][3] = fmaxf(acc[t][3] + bls[c + 1], 0.f);
    }

    if (!HEAD) {
#pragma unroll
        for (int t = 0; t < 8; t++) {
            const int c = 8 * t + cb;
            *(__half2*)(SA + r0 * 144 + c * 2) = __floats2half2_rn(acc[t][0], acc[t][1]);
            *(__half2*)(SA + r1 * 144 + c * 2) = __floats2half2_rn(acc[t][2], acc[t][3]);
        }
        __syncthreads();
        for (int i = tid; i < 1024; i += 256) {
            const int row = i >> 3, c8 = i & 7;
            if (base + row < N)
                *(uint4*)((__half*)outp + (size_t)(base + row) * D + c8 * 8) =
                    *(uint4*)(SA + row * 144 + c8 * 16);
        }
    } else {
#pragma unroll
        for (int t = 0; t < 8; t++) {
            *(__half2*)(SA + r0 * 128 + ((t ^ (r0 & 7)) << 4) + cb * 2) =
                __floats2half2_rn(acc[t][0], acc[t][1]);
            *(__half2*)(SA + r1 * 128 + ((t ^ (r1 & 7)) << 4) + cb * 2) =
                __floats2half2_rn(acc[t][2], acc[t][3]);
        }
        for (int i = tid; i < 512; i += 256) {
            const int row = i >> 3, c = i & 7;
            float4 f0 = *(const float4*)(Wo + row * D + c * 8);
            float4 f1 = *(const float4*)(Wo + row * D + c * 8 + 4);
            *(uint4*)(SB + row * 128 + ((c ^ (row & 7)) << 4)) = pack8h(f0, f1);
        }
        __syncthreads();

        float ac2[8][4];
#pragma unroll
        for (int t = 0; t < 8; t++)
            ac2[t][0] = ac2[t][1] = ac2[t][2] = ac2[t][3] = 0.f;
#pragma unroll
        for (int t = 0; t < 4; t++) {
            uint32_t a0, a1, a2, a3;
            uint32_t aaddr = smem_u32(SA + arow * 128 + (((2 * t + ac) ^ (arow & 7)) << 4));
            LDSM_X4(a0, a1, a2, a3, aaddr);
#pragma unroll
            for (int p = 0; p < 4; p++) {
                const int nn = bn + 16 * p;
                uint32_t baddr = smem_u32(SB + nn * 128 + (((2 * t + bc) ^ (nn & 7)) << 4));
                uint32_t b0, b1, b2, b3;
                LDSM_X4(b0, b1, b2, b3, baddr);
                mma16816(ac2[2 * p + 0], a0, a1, a2, a3, b0, b1);
                mma16816(ac2[2 * p + 1], a0, a1, a2, a3, b2, b3);
            }
        }
        __syncthreads();

#pragma unroll
        for (int t = 0; t < 8; t++) {
            const int c = 8 * t + cb;
            *(float2*)(smem + r0 * 264 + c * 4) =
                make_float2(ac2[t][0] + bos[c], ac2[t][1] + bos[c + 1]);
            *(float2*)(smem + r1 * 264 + c * 4) =
                make_float2(ac2[t][2] + bos[c], ac2[t][3] + bos[c + 1]);
        }
        __syncthreads();

        if (tid < 128) {
            const float* lr = (const float*)(smem + tid * 264);
            float mx = -1e30f;
#pragma unroll
            for (int c = 0; c < 64; c++) mx = fmaxf(mx, lr[c]);
            float sm = 0.f;
#pragma unroll
            for (int c = 0; c < 64; c++) sm += expf(lr[c] - mx);
            const float lse = mx + logf(sm);
            const int n = base + tid;
            if (n < N) {
                float* op = (float*)outp + (size_t)n * D;
#pragma unroll
                for (int c = 0; c < 64; c += 4) {
                    float4 r = make_float4(lr[c] - lse, lr[c + 1] - lse,
                                           lr[c + 2] - lse, lr[c + 3] - lse);
                    *(float4*)(op + c) = r;
                }
            }
        }
    }
}

// ---------------------------------------------------------------------------
extern "C" void kernel_launch(void* const* d_in, const int* in_sizes, int n_in,
                              void* d_out, int out_size) {
    const float* x    = (const float*)d_in[0];
    const void*  ei   = d_in[1];
    const float* W1l  = (const float*)d_in[2];
    const float* b1l  = (const float*)d_in[3];
    const float* W1r  = (const float*)d_in[4];
    const float* W2l  = (const float*)d_in[5];
    const float* b2l  = (const float*)d_in[6];
    const float* W2r  = (const float*)d_in[7];
    const float* Wout = (const float*)d_in[8];
    const float* bout = (const float*)d_in[9];

    const int N = in_sizes[0] / D;
    const int E = in_sizes[1] / 2;

    int*   cnt;  cudaGetSymbolAddress((void**)&cnt,  g_cnt);
    int*   ptr;  cudaGetSymbolAddress((void**)&ptr,  g_ptr);
    int*   cur;  cudaGetSymbolAddress((void**)&cur,  g_cur);
    unsigned long long* flag; cudaGetSymbolAddress((void**)&flag, g_flag);
    int*   csr;  cudaGetSymbolAddress((void**)&csr,  g_csr);
    __half* mean; cudaGetSymbolAddress((void**)&mean, g_mean);
    __half* xh;  cudaGetSymbolAddress((void**)&xh,   g_xh);
    __half* h1;  cudaGetSymbolAddress((void**)&h1,   g_h1);

    const int SMEM_MMA = 49152 + 512;

    cudaStreamCaptureStatus cs = cudaStreamCaptureStatusNone;
    cudaStreamIsCapturing(0, &cs);
    if (cs == cudaStreamCaptureStatusNone) {
        cudaFuncSetAttribute(hmma_transform<false>,
                             cudaFuncAttributeMaxDynamicSharedMemorySize, SMEM_MMA);
        cudaFuncSetAttribute(hmma_transform<true>,
                             cudaFuncAttributeMaxDynamicSharedMemorySize, SMEM_MMA);
    }

    const int nb = (N + 1023) / 1024;
    const int e4blocks = ((E + 3) / 4 + 255) / 256;   // 4 edges/thread
    const int gblocks = (N * 8 + 255) / 256;          // 8 lanes/node
    const int mblocks = (N + 127) / 128;

    // CSR build: [0] hist + x->fp16, [1] scan, [2] scatter(+state reset)
    hist_kernel<<<e4blocks, 256>>>(ei, cnt, x, xh, N * D / 4, E);
    scan_kernel<<<nb, 256>>>(cnt, ptr, cur, flag, N, E);
    scatter_kernel<<<e4blocks, 256>>>(ei, cur, csr, cnt, flag, N, E);

    // Layer 1: [3] gather (profiled), [4] HMMA transform -> fp16 h1
    gather_mean<<<gblocks, 256>>>(xh, ptr, csr, mean, N, E);
    hmma_transform<false><<<mblocks, 256, SMEM_MMA>>>(
        mean, xh, W1l, b1l, W1r, nullptr, nullptr, h1, N);
    // Layer 2 + head: [5] gather, [6] HMMA transform + head + log_softmax
    gather_mean<<<gblocks, 256>>>(h1, ptr, csr, mean, N, E);
    hmma_transform<true><<<mblocks, 256, SMEM_MMA>>>(
        mean, h1, W2l, b2l, W2r, Wout, bout, (float*)d_out, N);
}

// round 15
// speedup vs baseline: 1.2789x; 1.1000x over previous
#include <cuda_runtime.h>
#include <cuda_fp16.h>
#include <math.h>
#include <stdint.h>

// GraphSAGE encoder, fully fused layers:
//   CSR build (3 launches) -> fused [gather/mean -> HMMA transform] per layer
//   (layer 2 additionally fuses output head GEMM + log_softmax).
// 5 launches total. Gather writes mean directly into the swizzled SMEM A-tile.
// NOTE: tcgen05 unusable — harness ptxas targets sm_103 (no 'a').
// N=100000, E=1600000, D=64.
// State invariant: g_cnt and g_flag are zero at entry to each kernel_launch
// (zero-init at load; scatter_kernel re-zeroes them for the next replay).

#define MAXN 100000
#define MAXE 1600000
#define D 64

__device__ int                g_cnt[MAXN];
__device__ int                g_ptr[MAXN + 1];
__device__ int                g_cur[MAXN];
__device__ unsigned long long g_flag[128];
__device__ int                g_csr[MAXE];
__device__ __half             g_xh[MAXN * D];   // fp16 copy of x
__device__ __half             g_h1[MAXN * D];   // layer-1 activations (fp16)
__device__ __align__(16) __half g_zero[64];     // stays zero (never written)

// ---------------- small helpers ----------------
__device__ __forceinline__ void st4h(__half* p, float x, float y, float z, float w) {
    __half2 h0 = __floats2half2_rn(x, y);
    __half2 h1 = __floats2half2_rn(z, w);
    uint2 u;
    u.x = *reinterpret_cast<unsigned*>(&h0);
    u.y = *reinterpret_cast<unsigned*>(&h1);
    *reinterpret_cast<uint2*>(p) = u;
}
__device__ __forceinline__ uint4 pack8h(float4 f0, float4 f1) {
    __half2 h0 = __floats2half2_rn(f0.x, f0.y);
    __half2 h1 = __floats2half2_rn(f0.z, f0.w);
    __half2 h2 = __floats2half2_rn(f1.x, f1.y);
    __half2 h3 = __floats2half2_rn(f1.z, f1.w);
    uint4 u;
    u.x = *reinterpret_cast<unsigned*>(&h0);
    u.y = *reinterpret_cast<unsigned*>(&h1);
    u.z = *reinterpret_cast<unsigned*>(&h2);
    u.w = *reinterpret_cast<unsigned*>(&h3);
    return u;
}
__device__ __forceinline__ __half2 u2h2(unsigned v) {
    return *reinterpret_cast<const __half2*>(&v);
}
__device__ __forceinline__ uint32_t smem_u32(const void* p) {
    uint32_t a;
    asm("{ .reg .u64 t; cvta.to.shared.u64 t, %1; cvt.u32.u64 %0, t; }"
        : "=r"(a) : "l"(p));
    return a;
}
#define LDSM_X4(r0, r1, r2, r3, addr) \
    asm volatile("ldmatrix.sync.aligned.m8n8.x4.shared.b16 {%0,%1,%2,%3}, [%4];" \
                 : "=r"(r0), "=r"(r1), "=r"(r2), "=r"(r3) : "r"(addr))
__device__ __forceinline__ void mma16816(float* d, uint32_t a0, uint32_t a1,
                                         uint32_t a2, uint32_t a3,
                                         uint32_t b0, uint32_t b1) {
    asm volatile("mma.sync.aligned.m16n8k16.row.col.f32.f16.f16.f32 "
                 "{%0,%1,%2,%3}, {%4,%5,%6,%7}, {%8,%9}, {%0,%1,%2,%3};"
                 : "+f"(d[0]), "+f"(d[1]), "+f"(d[2]), "+f"(d[3])
                 : "r"(a0), "r"(a1), "r"(a2), "r"(a3), "r"(b0), "r"(b1));
}

__device__ __forceinline__ int detect_is64_block(const int* ei32) {
    __shared__ int s_is64;
    if (threadIdx.x == 0) {
        int az = 1;
#pragma unroll
        for (int t = 0; t < 8; t++) az &= (ei32[2 * t + 1] == 0);
        s_is64 = az;
    }
    __syncthreads();
    return s_is64;
}

// ---------------- CSR build (4 edges per thread) ----------------
__global__ void hist_kernel(const void* __restrict__ ei, int* __restrict__ cnt,
                            const float* __restrict__ x, __half* __restrict__ xh,
                            int nquads, int E) {
    const int is64 = detect_is64_block((const int*)ei);
    const int gid = blockIdx.x * blockDim.x + threadIdx.x;
    const int stride = gridDim.x * blockDim.x;
    for (int i = gid; i < nquads; i += stride) {
        float4 v = reinterpret_cast<const float4*>(x)[i];
        st4h(xh + (size_t)i * 4, v.x, v.y, v.z, v.w);
    }
    const int e0 = gid * 4;
    if (e0 >= E) return;
    if (e0 + 3 < E) {
        int d0, d1, d2, d3;
        if (is64) {
            const longlong2* p = (const longlong2*)((const long long*)ei + E + e0);
            longlong2 a = p[0], b = p[1];
            d0 = (int)a.x; d1 = (int)a.y; d2 = (int)b.x; d3 = (int)b.y;
        } else {
            int4 a = *(const int4*)((const int*)ei + E + e0);
            d0 = a.x; d1 = a.y; d2 = a.z; d3 = a.w;
        }
        atomicAdd(&cnt[d0], 1);
        atomicAdd(&cnt[d1], 1);
        atomicAdd(&cnt[d2], 1);
        atomicAdd(&cnt[d3], 1);
    } else {
        for (int e = e0; e < E; e++) {
            int d = is64 ? (int)((const long long*)ei)[(long long)E + e]
                         : ((const int*)ei)[(long long)E + e];
            atomicAdd(&cnt[d], 1);
        }
    }
}

__global__ void scan_kernel(const int* __restrict__ cnt, int* __restrict__ ptr,
                            int* __restrict__ cur, unsigned long long* __restrict__ flag,
                            int N, int E) {
    __shared__ int ssum[256];
    const int tid = threadIdx.x;
    const int b = blockIdx.x;
    const int base = b * 1024 + tid * 4;

    int v0 = (base + 0 < N) ? cnt[base + 0] : 0;
    int v1 = (base + 1 < N) ? cnt[base + 1] : 0;
    int v2 = (base + 2 < N) ? cnt[base + 2] : 0;
    int v3 = (base + 3 < N) ? cnt[base + 3] : 0;
    int s = v0 + v1 + v2 + v3;
    ssum[tid] = s;
    __syncthreads();
    for (int st = 1; st < 256; st <<= 1) {
        int t = (tid >= st) ? ssum[tid - st] : 0;
        __syncthreads();
        ssum[tid] += t;
        __syncthreads();
    }
    const int my_incl = ssum[tid];
    const int total = ssum[255];

    if (tid == 0)
        atomicExch(&flag[b], (((unsigned long long)(unsigned)total) << 1) | 1ull);

    int agg = 0;
    if (tid < b) {
        unsigned long long f;
        do { f = atomicAdd(&flag[tid], 0ull); } while (!(f & 1ull));
        agg = (int)(f >> 1);
    }
    __syncthreads();
    ssum[tid] = agg;
    __syncthreads();
    for (int st = 128; st; st >>= 1) {
        if (tid < st) ssum[tid] += ssum[tid + st];
        __syncthreads();
    }
    const int prev = ssum[0];

    int off = prev + my_incl - s;
    if (base + 0 < N) { ptr[base + 0] = off; cur[base + 0] = off; }  off += v0;
    if (base + 1 < N) { ptr[base + 1] = off; cur[base + 1] = off; }  off += v1;
    if (base + 2 < N) { ptr[base + 2] = off; cur[base + 2] = off; }  off += v2;
    if (base + 3 < N) { ptr[base + 3] = off; cur[base + 3] = off; }
    if (b == 0 && tid == 0) ptr[N] = E;
}

__global__ void scatter_kernel(const void* __restrict__ ei, int* __restrict__ cur,
                               int* __restrict__ csr, int* __restrict__ cnt,
                               unsigned long long* __restrict__ flag, int N, int E) {
    const int is64 = detect_is64_block((const int*)ei);
    const int gid = blockIdx.x * blockDim.x + threadIdx.x;
    if (gid < 128) flag[gid] = 0ull;
    if (gid < N) cnt[gid] = 0;
    const int e0 = gid * 4;
    if (e0 >= E) return;
    if (e0 + 3 < E) {
        int s0, s1, s2, s3, d0, d1, d2, d3;
        if (is64) {
            const longlong2* ps = (const longlong2*)((const long long*)ei + e0);
            const longlong2* pd = (const longlong2*)((const long long*)ei + E + e0);
            longlong2 a = ps[0], b = ps[1], c = pd[0], d = pd[1];
            s0 = (int)a.x; s1 = (int)a.y; s2 = (int)b.x; s3 = (int)b.y;
            d0 = (int)c.x; d1 = (int)c.y; d2 = (int)d.x; d3 = (int)d.y;
        } else {
            int4 a = *(const int4*)((const int*)ei + e0);
            int4 c = *(const int4*)((const int*)ei + E + e0);
            s0 = a.x; s1 = a.y; s2 = a.z; s3 = a.w;
            d0 = c.x; d1 = c.y; d2 = c.z; d3 = c.w;
        }
        csr[atomicAdd(&cur[d0], 1)] = s0;
        csr[atomicAdd(&cur[d1], 1)] = s1;
        csr[atomicAdd(&cur[d2], 1)] = s2;
        csr[atomicAdd(&cur[d3], 1)] = s3;
    } else {
        for (int e = e0; e < E; e++) {
            int s, d;
            if (is64) {
                s = (int)((const long long*)ei)[e];
                d = (int)((const long long*)ei)[(long long)E + e];
            } else {
                s = ((const int*)ei)[e];
                d = ((const int*)ei)[(long long)E + e];
            }
            csr[atomicAdd(&cur[d], 1)] = s;
        }
    }
}

// ---------------- fused layer: gather/mean -> HMMA transform -----------------
// 256 threads, one 128-node tile per CTA.
// Phase 1: 32 groups of 8 lanes; group g gathers nodes 4g..4g+3 (R14 pipelined
//   MLP-8 loop, fp16 accumulation) and writes the mean straight into the
//   swizzled SMEM A-tile (chunks 0-7). Self features (chunks 8-15) and the
//   [Wl|Wr] B-tile are staged from global.
// Phase 2: mma.sync m16n8k16 over K=128; bias+relu.
//   !HEAD: store h fp16.  HEAD: second GEMM h@Wo^T (K=64) + log_softmax.
template<bool HEAD>
__global__ void __launch_bounds__(256) fused_layer(
    const __half* __restrict__ feat,          // gather + self source (xh or h1)
    const int* __restrict__ ptr, const int* __restrict__ csr,
    const float* __restrict__ Wl, const float* __restrict__ bl,
    const float* __restrict__ Wr, const float* __restrict__ Wo,
    const float* __restrict__ bo, void* __restrict__ outp, int N, int E)
{
    extern __shared__ char smem[];
    char* SA = smem;                               // 32768 B
    char* SB = smem + 32768;                       // 16384 B
    float* bls = (float*)(smem + 49152);
    float* bos = (float*)(smem + 49408);

    const int tid = threadIdx.x;
    const int w = tid >> 5, lane = tid & 31;
    const int base = blockIdx.x * 128;

    if (tid < 64) { bls[tid] = bl[tid]; if (HEAD) bos[tid] = bo[tid]; }

    // ---- stage B: [Wl | Wr] as 64x128 fp16 ----
    for (int i = tid; i < 1024; i += 256) {
        const int row = i >> 4, c = i & 15;
        const float* src = (c < 8) ? (Wl + row * D + c * 8)
                                   : (Wr + row * D + (c - 8) * 8);
        float4 f0 = *(const float4*)src;
        float4 f1 = *(const float4*)(src + 4);
        *(uint4*)(SB + row * 256 + ((c ^ (row & 7)) << 4)) = pack8h(f0, f1);
    }

    // ---- stage A chunks 8-15: self features ----
    for (int i = tid; i < 1024; i += 256) {
        const int row = i >> 3, c = (i & 7) + 8;
        const int n = base + row;
        uint4 val = make_uint4(0u, 0u, 0u, 0u);
        if (n < N) val = *(const uint4*)(feat + (size_t)n * D + (c - 8) * 8);
        *(uint4*)(SA + row * 256 + ((c ^ (row & 7)) << 4)) = val;
    }

    // ---- gather phase: group g (8 lanes), nodes 4g..4g+3 -> A chunks 0-7 ----
    {
        const int g = tid >> 3;
        const int q = tid & 7;
        const unsigned gmask = 0xFFu << (threadIdx.x & 24);
        const __half* fq = feat + q * 8;
        const __half* zq = g_zero + q * 8;
        const int elim = E - 1;

#pragma unroll 1
        for (int v = 0; v < 4; v++) {
            const int row = 4 * g + v;
            const int n = base + row;
            int rs = 0, re = 0;
            if (n < N) { rs = ptr[n]; re = ptr[n + 1]; }

            __half2 c0 = __floats2half2_rn(0.f, 0.f), c1 = c0, c2 = c0, c3 = c0;
            int b = rs;
            int idx = (b < re) ? csr[min(b + q, elim)] : 0;
#pragma unroll 1
            for (; b + 8 <= re; b += 8) {
                const int idx_c = idx;
                idx = csr[min(b + 8 + q, elim)];
                int s0 = __shfl_sync(gmask, idx_c, 0, 8);
                int s1 = __shfl_sync(gmask, idx_c, 1, 8);
                int s2 = __shfl_sync(gmask, idx_c, 2, 8);
                int s3 = __shfl_sync(gmask, idx_c, 3, 8);
                int s4 = __shfl_sync(gmask, idx_c, 4, 8);
                int s5 = __shfl_sync(gmask, idx_c, 5, 8);
                int s6 = __shfl_sync(gmask, idx_c, 6, 8);
                int s7 = __shfl_sync(gmask, idx_c, 7, 8);
                uint4 v0 = *(const uint4*)(fq + (size_t)s0 * D);
                uint4 v1 = *(const uint4*)(fq + (size_t)s1 * D);
                uint4 v2 = *(const uint4*)(fq + (size_t)s2 * D);
                uint4 v3 = *(const uint4*)(fq + (size_t)s3 * D);
                uint4 v4 = *(const uint4*)(fq + (size_t)s4 * D);
                uint4 v5 = *(const uint4*)(fq + (size_t)s5 * D);
                uint4 v6 = *(const uint4*)(fq + (size_t)s6 * D);
                uint4 v7 = *(const uint4*)(fq + (size_t)s7 * D);
                c0 = __hadd2(c0, u2h2(v0.x)); c1 = __hadd2(c1, u2h2(v0.y));
                c2 = __hadd2(c2, u2h2(v0.z)); c3 = __hadd2(c3, u2h2(v0.w));
                c0 = __hadd2(c0, u2h2(v1.x)); c1 = __hadd2(c1, u2h2(v1.y));
                c2 = __hadd2(c2, u2h2(v1.z)); c3 = __hadd2(c3, u2h2(v1.w));
                c0 = __hadd2(c0, u2h2(v2.x)); c1 = __hadd2(c1, u2h2(v2.y));
                c2 = __hadd2(c2, u2h2(v2.z)); c3 = __hadd2(c3, u2h2(v2.w));
                c0 = __hadd2(c0, u2h2(v3.x)); c1 = __hadd2(c1, u2h2(v3.y));
                c2 = __hadd2(c2, u2h2(v3.z)); c3 = __hadd2(c3, u2h2(v3.w));
                c0 = __hadd2(c0, u2h2(v4.x)); c1 = __hadd2(c1, u2h2(v4.y));
                c2 = __hadd2(c2, u2h2(v4.z)); c3 = __hadd2(c3, u2h2(v4.w));
                c0 = __hadd2(c0, u2h2(v5.x)); c1 = __hadd2(c1, u2h2(v5.y));
                c2 = __hadd2(c2, u2h2(v5.z)); c3 = __hadd2(c3, u2h2(v5.w));
                c0 = __hadd2(c0, u2h2(v6.x)); c1 = __hadd2(c1, u2h2(v6.y));
                c2 = __hadd2(c2, u2h2(v6.z)); c3 = __hadd2(c3, u2h2(v6.w));
                c0 = __hadd2(c0, u2h2(v7.x)); c1 = __hadd2(c1, u2h2(v7.y));
                c2 = __hadd2(c2, u2h2(v7.z)); c3 = __hadd2(c3, u2h2(v7.w));
            }
            if (b < re) {
                const int cnt = re - b;
                int s0 = __shfl_sync(gmask, idx, 0, 8);
                int s1 = __shfl_sync(gmask, idx, 1, 8);
                int s2 = __shfl_sync(gmask, idx, 2, 8);
                int s3 = __shfl_sync(gmask, idx, 3, 8);
                int s4 = __shfl_sync(gmask, idx, 4, 8);
                int s5 = __shfl_sync(gmask, idx, 5, 8);
                int s6 = __shfl_sync(gmask, idx, 6, 8);
                int s7 = __shfl_sync(gmask, idx, 7, 8);
                const __half* p0 = (0 < cnt) ? fq + (size_t)s0 * D : zq;
                const __half* p1 = (1 < cnt) ? fq + (size_t)s1 * D : zq;
                const __half* p2 = (2 < cnt) ? fq + (size_t)s2 * D : zq;
                const __half* p3 = (3 < cnt) ? fq + (size_t)s3 * D : zq;
                const __half* p4 = (4 < cnt) ? fq + (size_t)s4 * D : zq;
                const __half* p5 = (5 < cnt) ? fq + (size_t)s5 * D : zq;
                const __half* p6 = (6 < cnt) ? fq + (size_t)s6 * D : zq;
                const __half* p7 = (7 < cnt) ? fq + (size_t)s7 * D : zq;
                uint4 v0 = *(const uint4*)p0;
                uint4 v1 = *(const uint4*)p1;
                uint4 v2 = *(const uint4*)p2;
                uint4 v3 = *(const uint4*)p3;
                uint4 v4 = *(const uint4*)p4;
                uint4 v5 = *(const uint4*)p5;
                uint4 v6 = *(const uint4*)p6;
                uint4 v7 = *(const uint4*)p7;
                c0 = __hadd2(c0, u2h2(v0.x)); c1 = __hadd2(c1, u2h2(v0.y));
                c2 = __hadd2(c2, u2h2(v0.z)); c3 = __hadd2(c3, u2h2(v0.w));
                c0 = __hadd2(c0, u2h2(v1.x)); c1 = __hadd2(c1, u2h2(v1.y));
                c2 = __hadd2(c2, u2h2(v1.z)); c3 = __hadd2(c3, u2h2(v1.w));
                c0 = __hadd2(c0, u2h2(v2.x)); c1 = __hadd2(c1, u2h2(v2.y));
                c2 = __hadd2(c2, u2h2(v2.z)); c3 = __hadd2(c3, u2h2(v2.w));
                c0 = __hadd2(c0, u2h2(v3.x)); c1 = __hadd2(c1, u2h2(v3.y));
                c2 = __hadd2(c2, u2h2(v3.z)); c3 = __hadd2(c3, u2h2(v3.w));
                c0 = __hadd2(c0, u2h2(v4.x)); c1 = __hadd2(c1, u2h2(v4.y));
                c2 = __hadd2(c2, u2h2(v4.z)); c3 = __hadd2(c3, u2h2(v4.w));
                c0 = __hadd2(c0, u2h2(v5.x)); c1 = __hadd2(c1, u2h2(v5.y));
                c2 = __hadd2(c2, u2h2(v5.z)); c3 = __hadd2(c3, u2h2(v5.w));
                c0 = __hadd2(c0, u2h2(v6.x)); c1 = __hadd2(c1, u2h2(v6.y));
                c2 = __hadd2(c2, u2h2(v6.z)); c3 = __hadd2(c3, u2h2(v6.w));
                c0 = __hadd2(c0, u2h2(v7.x)); c1 = __hadd2(c1, u2h2(v7.y));
                c2 = __hadd2(c2, u2h2(v7.z)); c3 = __hadd2(c3, u2h2(v7.w));
            }
            float2 f0 = __half22float2(c0);
            float2 f1 = __half22float2(c1);
            float2 f2 = __half22float2(c2);
            float2 f3 = __half22float2(c3);
            const float invd = 1.0f / fmaxf((float)(re - rs), 1.0f);
            uint4 m = pack8h(
                make_float4(f0.x * invd, f0.y * invd, f1.x * invd, f1.y * invd),
                make_float4(f2.x * invd, f2.y * invd, f3.x * invd, f3.y * invd));
            *(uint4*)(SA + row * 256 + ((q ^ (row & 7)) << 4)) = m;
        }
    }
    __syncthreads();

    // ---- MMA 1: per warp rows [16w,16w+16), 8 n-tiles, 8 k-tiles ----
    float acc[8][4];
#pragma unroll
    for (int t = 0; t < 8; t++)
        acc[t][0] = acc[t][1] = acc[t][2] = acc[t][3] = 0.f;

    const int arow = 16 * w + (lane & 15);
    const int ac = lane >> 4;
    const int bn = (lane & 7) + ((lane >> 4) << 3);
    const int bc = (lane >> 3) & 1;

#pragma unroll
    for (int t = 0; t < 8; t++) {
        uint32_t a0, a1, a2, a3;
        uint32_t aaddr = smem_u32(SA + arow * 256 + (((2 * t + ac) ^ (arow & 7)) << 4));
        LDSM_X4(a0, a1, a2, a3, aaddr);
#pragma unroll
        for (int p = 0; p < 4; p++) {
            const int nn = bn + 16 * p;
            uint32_t baddr = smem_u32(SB + nn * 256 + (((2 * t + bc) ^ (nn & 7)) << 4));
            uint32_t b0, b1, b2, b3;
            LDSM_X4(b0, b1, b2, b3, baddr);
            mma16816(acc[2 * p + 0], a0, a1, a2, a3, b0, b1);
            mma16816(acc[2 * p + 1], a0, a1, a2, a3, b2, b3);
        }
    }
    __syncthreads();

    const int r0 = 16 * w + (lane >> 2);
    const int r1 = r0 + 8;
    const int cb = 2 * (lane & 3);
#pragma unroll
    for (int t = 0; t < 8; t++) {
        const int c = 8 * t + cb;
        acc[t][0] = fmaxf(acc[t][0] + bls[c],     0.f);
        acc[t][1] = fmaxf(acc[t][1] + bls[c + 1], 0.f);
        acc[t][2] = fmaxf(acc[t][2] + bls[c],     0.f);
        acc[t][3] = fmaxf(acc[t][3] + bls[c + 1], 0.f);
    }

    if (!HEAD) {
#pragma unroll
        for (int t = 0; t < 8; t++) {
            const int c = 8 * t + cb;
            *(__half2*)(SA + r0 * 144 + c * 2) = __floats2half2_rn(acc[t][0], acc[t][1]);
            *(__half2*)(SA + r1 * 144 + c * 2) = __floats2half2_rn(acc[t][2], acc[t][3]);
        }
        __syncthreads();
        for (int i = tid; i < 1024; i += 256) {
            const int row = i >> 3, c8 = i & 7;
            if (base + row < N)
                *(uint4*)((__half*)outp + (size_t)(base + row) * D + c8 * 8) =
                    *(uint4*)(SA + row * 144 + c8 * 16);
        }
    } else {
#pragma unroll
        for (int t = 0; t < 8; t++) {
            *(__half2*)(SA + r0 * 128 + ((t ^ (r0 & 7)) << 4) + cb * 2) =
                __floats2half2_rn(acc[t][0], acc[t][1]);
            *(__half2*)(SA + r1 * 128 + ((t ^ (r1 & 7)) << 4) + cb * 2) =
                __floats2half2_rn(acc[t][2], acc[t][3]);
        }
        for (int i = tid; i < 512; i += 256) {
            const int row = i >> 3, c = i & 7;
            float4 f0 = *(const float4*)(Wo + row * D + c * 8);
            float4 f1 = *(const float4*)(Wo + row * D + c * 8 + 4);
            *(uint4*)(SB + row * 128 + ((c ^ (row & 7)) << 4)) = pack8h(f0, f1);
        }
        __syncthreads();

        float ac2[8][4];
#pragma unroll
        for (int t = 0; t < 8; t++)
            ac2[t][0] = ac2[t][1] = ac2[t][2] = ac2[t][3] = 0.f;
#pragma unroll
        for (int t = 0; t < 4; t++) {
            uint32_t a0, a1, a2, a3;
            uint32_t aaddr = smem_u32(SA + arow * 128 + (((2 * t + ac) ^ (arow & 7)) << 4));
            LDSM_X4(a0, a1, a2, a3, aaddr);
#pragma unroll
            for (int p = 0; p < 4; p++) {
                const int nn = bn + 16 * p;
                uint32_t baddr = smem_u32(SB + nn * 128 + (((2 * t + bc) ^ (nn & 7)) << 4));
                uint32_t b0, b1, b2, b3;
                LDSM_X4(b0, b1, b2, b3, baddr);
                mma16816(ac2[2 * p + 0], a0, a1, a2, a3, b0, b1);
                mma16816(ac2[2 * p + 1], a0, a1, a2, a3, b2, b3);
            }
        }
        __syncthreads();

#pragma unroll
        for (int t = 0; t < 8; t++) {
            const int c = 8 * t + cb;
            *(float2*)(smem + r0 * 264 + c * 4) =
                make_float2(ac2[t][0] + bos[c], ac2[t][1] + bos[c + 1]);
            *(float2*)(smem + r1 * 264 + c * 4) =
                make_float2(ac2[t][2] + bos[c], ac2[t][3] + bos[c + 1]);
        }
        __syncthreads();

        if (tid < 128) {
            const float* lr = (const float*)(smem + tid * 264);
            float mx = -1e30f;
#pragma unroll
            for (int c = 0; c < 64; c++) mx = fmaxf(mx, lr[c]);
            float sm = 0.f;
#pragma unroll
            for (int c = 0; c < 64; c++) sm += expf(lr[c] - mx);
            const float lse = mx + logf(sm);
            const int n = base + tid;
            if (n < N) {
                float* op = (float*)outp + (size_t)n * D;
#pragma unroll
                for (int c = 0; c < 64; c += 4) {
                    float4 r = make_float4(lr[c] - lse, lr[c + 1] - lse,
                                           lr[c + 2] - lse, lr[c + 3] - lse);
                    *(float4*)(op + c) = r;
                }
            }
        }
    }
}

// ---------------------------------------------------------------------------
extern "C" void kernel_launch(void* const* d_in, const int* in_sizes, int n_in,
                              void* d_out, int out_size) {
    const float* x    = (const float*)d_in[0];
    const void*  ei   = d_in[1];
    const float* W1l  = (const float*)d_in[2];
    const float* b1l  = (const float*)d_in[3];
    const float* W1r  = (const float*)d_in[4];
    const float* W2l  = (const float*)d_in[5];
    const float* b2l  = (const float*)d_in[6];
    const float* W2r  = (const float*)d_in[7];
    const float* Wout = (const float*)d_in[8];
    const float* bout = (const float*)d_in[9];

    const int N = in_sizes[0] / D;
    const int E = in_sizes[1] / 2;

    int*   cnt;  cudaGetSymbolAddress((void**)&cnt,  g_cnt);
    int*   ptr;  cudaGetSymbolAddress((void**)&ptr,  g_ptr);
    int*   cur;  cudaGetSymbolAddress((void**)&cur,  g_cur);
    unsigned long long* flag; cudaGetSymbolAddress((void**)&flag, g_flag);
    int*   csr;  cudaGetSymbolAddress((void**)&csr,  g_csr);
    __half* xh;  cudaGetSymbolAddress((void**)&xh,   g_xh);
    __half* h1;  cudaGetSymbolAddress((void**)&h1,   g_h1);

    const int SMEM_MMA = 49152 + 512;

    cudaStreamCaptureStatus cs = cudaStreamCaptureStatusNone;
    cudaStreamIsCapturing(0, &cs);
    if (cs == cudaStreamCaptureStatusNone) {
        cudaFuncSetAttribute(fused_layer<false>,
                             cudaFuncAttributeMaxDynamicSharedMemorySize, SMEM_MMA);
        cudaFuncSetAttribute(fused_layer<true>,
                             cudaFuncAttributeMaxDynamicSharedMemorySize, SMEM_MMA);
    }

    const int nb = (N + 1023) / 1024;
    const int e4blocks = ((E + 3) / 4 + 255) / 256;   // 4 edges/thread
    const int mblocks = (N + 127) / 128;

    // CSR build: [0] hist + x->fp16, [1] scan, [2] scatter(+state reset)
    hist_kernel<<<e4blocks, 256>>>(ei, cnt, x, xh, N * D / 4, E);
    scan_kernel<<<nb, 256>>>(cnt, ptr, cur, flag, N, E);
    scatter_kernel<<<e4blocks, 256>>>(ei, cur, csr, cnt, flag, N, E);

    // Layer 1 fused: [3] (profiled) gather+transform -> fp16 h1
    fused_layer<false><<<mblocks, 256, SMEM_MMA>>>(
        xh, ptr, csr, W1l, b1l, W1r, nullptr, nullptr, h1, N, E);
    // Layer 2 fused + head: [4]
    fused_layer<true><<<mblocks, 256, SMEM_MMA>>>(
        h1, ptr, csr, W2l, b2l, W2r, Wout, bout, (float*)d_out, N, E);
}